// round 5
// baseline (speedup 1.0000x reference)
#include <cuda_runtime.h>
#include <cstdint>
#include <math.h>

#define NEGBIG -3.0e38f

// ---------------- scratch (device globals; no allocation allowed) ------------
__device__ float g_H[2048 * 576];    // cols 0:192 relu(fc1) = H0, 192:384 H1, 384:576 H2
__device__ float g_giC[2048 * 576];  // precomputed x@Wih_c^T + bih_c for current layer
__device__ float g_ghP[2048 * 576];  // precomputed x@Whh_p^T + bhh_p
__device__ float g_t0[2048 * 192];
__device__ float g_t1[2048 * 192];

// ---------------- generic fp32 tiled GEMM: C = act(A*B(+T) + bias) -----------
// A: MxK row-major (lda). BT=1: B is (N,K) row-major, use B^T. BT=0: B is (K,N).
// M%64==0, N%64==0, K%32==0.
template <int BT, int RELU>
__global__ void __launch_bounds__(256) gemm_kernel(
    const float* __restrict__ A, int lda,
    const float* __restrict__ B, const float* __restrict__ bias,
    float* __restrict__ C, int ldc, int M, int N, int K)
{
    __shared__ float As[64][33];
    __shared__ float Bs[32][65];
    const int tid = threadIdx.x;
    const int tx = tid & 15, ty = tid >> 4;
    const int bx = blockIdx.x, by = blockIdx.y;
    const int kl = tid & 31, rl = tid >> 5;
    float acc[4][4] = {};
    for (int k0 = 0; k0 < K; k0 += 32) {
        #pragma unroll
        for (int mm = 0; mm < 64; mm += 8)
            As[mm + rl][kl] = A[(size_t)(by * 64 + mm + rl) * lda + k0 + kl];
        if (BT) {
            #pragma unroll
            for (int nn = 0; nn < 64; nn += 8)
                Bs[kl][nn + rl] = B[(size_t)(bx * 64 + nn + rl) * K + k0 + kl];
        } else {
            const int nc = tid & 63, kr = tid >> 6;
            #pragma unroll
            for (int kk = 0; kk < 32; kk += 4)
                Bs[kk + kr][nc] = B[(size_t)(k0 + kk + kr) * N + bx * 64 + nc];
        }
        __syncthreads();
        #pragma unroll
        for (int kk = 0; kk < 32; kk++) {
            float a[4], bb[4];
            #pragma unroll
            for (int i = 0; i < 4; i++) a[i] = As[ty * 4 + i][kk];
            #pragma unroll
            for (int j = 0; j < 4; j++) bb[j] = Bs[kk][tx * 4 + j];
            #pragma unroll
            for (int i = 0; i < 4; i++)
                #pragma unroll
                for (int j = 0; j < 4; j++)
                    acc[i][j] = fmaf(a[i], bb[j], acc[i][j]);
        }
        __syncthreads();
    }
    #pragma unroll
    for (int i = 0; i < 4; i++) {
        const int row = by * 64 + ty * 4 + i;
        #pragma unroll
        for (int j = 0; j < 4; j++) {
            const int col = bx * 64 + tx * 4 + j;
            float v = acc[i][j] + bias[col];
            if (RELU) v = v > 0.f ? v : 0.f;
            C[(size_t)row * ldc + col] = v;
        }
    }
}

// ---------------- sequential scan: one 8-CTA cluster per batch ---------------
struct ScanArgs {
    const float* Hl;     // layer input, row stride 576 (col base folded in)
    const float* adj;    // (8,256,256)
    const float* smask;  // (8,256,256)
    const float* wk;     // (192,)
    const float* wr0;    // (192,192)
    const float* wr1;    // (192,192)
    const float* whhC;   // (576,192)
    const float* wihP;   // (576,192)
    const float* bhhC;   // (576,)
    const float* biP;    // (576,)
    const float* giC;    // (2048,576)
    const float* ghP;    // (2048,576)
    float* Hout;         // g_H + (l+1)*192, row stride 576
    float* attnL;        // attn out + l*65536; batch stride 131072, row stride 256
};

struct SmemScan {
    float GT[192][144];         // transposed gate weights: cols 0:72 whhC rows, 72:144 wihP rows
    float RT[192][49];          // transposed: 0:24 wr0, 24:48 wr1, 48 wk
    float V0[256][25];          // pitch 25 -> conflict-free column reads
    float V1[256][25];
    float Ksc[256];             // replicated per CTA
    float Attn[256];
    float Sm[256];
    alignas(16) float Mfull[192];
    alignas(16) float Hnew[192];
    float Mloc[24];
    float Hloc[24];
    float X24[24];
    float giCs[72];
    float ghPs[72];
    float Gres[144];
    float Gbias[144];
    float red[16];
};

__device__ __forceinline__ void st_remote(float* p, unsigned rank, float v) {
    unsigned laddr = (unsigned)__cvta_generic_to_shared(p);
    unsigned raddr;
    asm volatile("mapa.shared::cluster.u32 %0, %1, %2;" : "=r"(raddr) : "r"(laddr), "r"(rank));
    asm volatile("st.shared::cluster.f32 [%0], %1;" :: "r"(raddr), "f"(v) : "memory");
}

__device__ __forceinline__ void cluster_sync_all() {
    asm volatile("barrier.cluster.arrive.aligned;" ::: "memory");
    asm volatile("barrier.cluster.wait.aligned;" ::: "memory");
}

__device__ __forceinline__ float sigmf(float x) { return 1.f / (1.f + __expf(-x)); }

__global__ void __cluster_dims__(8, 1, 1) __launch_bounds__(256, 1) scan_kernel(ScanArgs A)
{
    extern __shared__ char smem_raw[];
    SmemScan& S = *reinterpret_cast<SmemScan*>(smem_raw);
    const int tid = threadIdx.x, warp = tid >> 5, lane = tid & 31;
    const int crank = blockIdx.x & 7, b = blockIdx.x >> 3, d0 = crank * 24;

    // ---- one-time init: transposed weight slices + zero state ----
    for (int idx = tid; idx < 192 * 144; idx += 256) {
        int k = idx / 144, o = idx % 144;
        int oo = (o < 72) ? o : o - 72;
        int g = oo / 24, d = oo % 24;
        const float* W = (o < 72) ? A.whhC : A.wihP;
        S.GT[k][o] = W[(size_t)(g * 192 + d0 + d) * 192 + k];
    }
    for (int idx = tid; idx < 192 * 49; idx += 256) {
        int k = idx / 49, o = idx % 49;
        float v;
        if (o < 24)      v = A.wr0[(size_t)(d0 + o) * 192 + k];
        else if (o < 48) v = A.wr1[(size_t)(d0 + o - 24) * 192 + k];
        else             v = A.wk[k];
        S.RT[k][o] = v;
    }
    if (tid < 144) {
        int oo = (tid < 72) ? tid : tid - 72;
        int g = oo / 24, d = oo % 24;
        S.Gbias[tid] = (tid < 72) ? A.bhhC[g * 192 + d0 + d] : A.biP[g * 192 + d0 + d];
    }
    for (int idx = tid; idx < 256 * 25; idx += 256) {
        (&S.V0[0][0])[idx] = 0.f;
        (&S.V1[0][0])[idx] = 0.f;
    }
    S.Ksc[tid] = 0.f;
    if (tid < 192) { S.Mfull[tid] = 0.f; S.Hnew[tid] = 0.f; }
    __syncthreads();
    cluster_sync_all();

    const size_t rb = (size_t)b * 256;
    for (int i = 0; i < 256; i++) {
        const size_t row = rb + i;
        // ---- prefetch step-local data ----
        if (tid < 72)       S.giCs[tid] = A.giC[row * 576 + (tid / 24) * 192 + d0 + (tid % 24)];
        else if (tid < 144) { int t = tid - 72; S.ghPs[t] = A.ghP[row * 576 + (t / 24) * 192 + d0 + (t % 24)]; }
        else if (tid < 168) S.X24[tid - 144] = A.Hl[row * 576 + d0 + (tid - 144)];
        S.Sm[tid] = A.smask[row * 256 + tid];
        float adjv = A.adj[row * 256 + tid];

        // ---- phase A: fold previous Hnew into V0/V1/Ksc (4-way k split) ----
        if (i > 0) {
            int o = tid >> 2, p = tid & 3;
            int o2 = (o < 49) ? o : 48;
            float s = 0.f;
            const float* hp = &S.Hnew[p * 48];
            #pragma unroll
            for (int k = 0; k < 48; k++) s = fmaf(hp[k], S.RT[p * 48 + k][o2], s);
            s += __shfl_xor_sync(0xffffffffu, s, 1);
            s += __shfl_xor_sync(0xffffffffu, s, 2);
            if (p == 0 && o < 49) {
                if (o < 24)      S.V0[i - 1][o] = s;
                else if (o < 48) S.V1[i - 1][o - 24] = s;
                else             S.Ksc[i - 1] = s;
            }
            if (tid >= 224 && tid < 248)
                A.Hout[(row - 1) * 576 + d0 + (tid - 224)] = S.Hnew[d0 + tid - 224];
        }
        __syncthreads();

        float* attnRow = A.attnL + (size_t)b * 131072 + (size_t)i * 256;
        if (i > 0) {
            // ---- masked softmax (wq/gat_b terms cancel) ----
            bool msk = (tid < i) && (adjv > 0.5f);
            float a = msk ? S.Ksc[tid] : NEGBIG;
            float m = a;
            #pragma unroll
            for (int o = 16; o; o >>= 1) m = fmaxf(m, __shfl_xor_sync(0xffffffffu, m, o));
            if (lane == 0) S.red[warp] = m;
            __syncthreads();
            if (tid == 0) {
                float v = S.red[0];
                #pragma unroll
                for (int w = 1; w < 8; w++) v = fmaxf(v, S.red[w]);
                S.red[8] = v;
            }
            __syncthreads();
            float e = __expf(a - S.red[8]);
            float su = e;
            #pragma unroll
            for (int o = 16; o; o >>= 1) su += __shfl_xor_sync(0xffffffffu, su, o);
            if (lane == 0) S.red[warp] = su;
            __syncthreads();
            if (tid == 0) {
                float v = 0.f;
                #pragma unroll
                for (int w = 0; w < 8; w++) v += S.red[w];
                S.red[9] = v;
            }
            __syncthreads();
            float attnv = e / S.red[9];
            S.Attn[tid] = attnv;
            if ((tid >> 5) == crank) attnRow[tid] = attnv;
            __syncthreads();

            // ---- M slice: warp-per-dim over j ----
            for (int dd = warp; dd < 24; dd += 8) {
                float s = 0.f;
                for (int j = lane; j < i; j += 32) {
                    float v1 = S.V1[j][dd];
                    float vr = fmaf(S.V0[j][dd] - v1, S.Sm[j], v1);
                    s = fmaf(S.Attn[j], vr, s);
                }
                #pragma unroll
                for (int o = 16; o; o >>= 1) s += __shfl_xor_sync(0xffffffffu, s, o);
                if (lane == 0) S.Mloc[dd] = s;
            }
            __syncthreads();
            if (tid < 192) st_remote(&S.Mfull[d0 + (tid >> 3)], tid & 7, S.Mloc[tid >> 3]);
        } else {
            if (tid < 192) S.Mfull[tid] = 0.f;
            if ((tid >> 5) == crank) attnRow[tid] = 0.f;
            __syncthreads();
        }
        cluster_sync_all();  // Mfull assembled in every CTA

        // ---- gates: gh_c = M@whhC^T (+bhh), gi_p = M@wihP^T (+bih) ----
        if (tid < 144) {
            float s0 = 0.f, s1 = 0.f, s2 = 0.f, s3 = 0.f;
            #pragma unroll
            for (int kk = 0; kk < 48; kk++) {
                float4 m4 = *reinterpret_cast<const float4*>(&S.Mfull[4 * kk]);
                s0 = fmaf(m4.x, S.GT[4 * kk + 0][tid], s0);
                s1 = fmaf(m4.y, S.GT[4 * kk + 1][tid], s1);
                s2 = fmaf(m4.z, S.GT[4 * kk + 2][tid], s2);
                s3 = fmaf(m4.w, S.GT[4 * kk + 3][tid], s3);
            }
            S.Gres[tid] = (s0 + s1) + (s2 + s3) + S.Gbias[tid];
        }
        __syncthreads();

        // ---- GRU pointwise: C (x,M) + P (M,x) ----
        if (tid < 24) {
            int d = tid;
            float rC = sigmf(S.giCs[d] + S.Gres[d]);
            float zC = sigmf(S.giCs[24 + d] + S.Gres[24 + d]);
            float nC = tanhf(S.giCs[48 + d] + rC * S.Gres[48 + d]);
            float Mv = S.Mfull[d0 + d];
            float Cc = (1.f - zC) * nC + zC * Mv;
            float rP = sigmf(S.Gres[72 + d] + S.ghPs[d]);
            float zP = sigmf(S.Gres[96 + d] + S.ghPs[24 + d]);
            float nP = tanhf(S.Gres[120 + d] + rP * S.ghPs[48 + d]);
            float Pp = (1.f - zP) * nP + zP * S.X24[d];
            S.Hloc[d] = Cc + Pp;
        }
        __syncthreads();
        if (tid < 192) st_remote(&S.Hnew[d0 + (tid >> 3)], tid & 7, S.Hloc[tid >> 3]);
        cluster_sync_all();  // Hnew assembled in every CTA
    }
    // final H row 255
    if (tid < 24) A.Hout[(rb + 255) * 576 + d0 + tid] = S.Hnew[d0 + tid];
}

// ------------------------------- launcher ------------------------------------
extern "C" void kernel_launch(void* const* d_in, const int* in_sizes, int n_in,
                              void* d_out, int out_size) {
    const float* features = (const float*)d_in[0];
    const float* adj      = (const float*)d_in[1];
    const float* smask    = (const float*)d_in[2];
    const float* fc1_w    = (const float*)d_in[5];
    const float* fc1_b    = (const float*)d_in[6];
    const float* gat_w    = (const float*)d_in[7];
    const float* wr0p     = (const float*)d_in[9];
    const float* wr1p     = (const float*)d_in[10];
    const float* gruc_wih = (const float*)d_in[11];
    const float* gruc_whh = (const float*)d_in[12];
    const float* gruc_bih = (const float*)d_in[13];
    const float* gruc_bhh = (const float*)d_in[14];
    const float* grup_wih = (const float*)d_in[15];
    const float* grup_whh = (const float*)d_in[16];
    const float* grup_bih = (const float*)d_in[17];
    const float* grup_bhh = (const float*)d_in[18];
    const float* mlp_w0   = (const float*)d_in[19];
    const float* mlp_b0   = (const float*)d_in[20];
    const float* mlp_w1   = (const float*)d_in[21];
    const float* mlp_b1   = (const float*)d_in[22];
    const float* mlp_w2   = (const float*)d_in[23];
    const float* mlp_b2   = (const float*)d_in[24];

    float* out = (float*)d_out;
    float* logits = out;                 // (8,256,192)
    float* attn = out + 8 * 256 * 192;   // (8,2,256,256)

    float *H, *GI, *GP, *T0, *T1;
    cudaGetSymbolAddress((void**)&H, g_H);
    cudaGetSymbolAddress((void**)&GI, g_giC);
    cudaGetSymbolAddress((void**)&GP, g_ghP);
    cudaGetSymbolAddress((void**)&T0, g_t0);
    cudaGetSymbolAddress((void**)&T1, g_t1);

    cudaFuncSetAttribute(scan_kernel, cudaFuncAttributeMaxDynamicSharedMemorySize,
                         (int)sizeof(SmemScan));

    dim3 blk(256);
    // H0 = relu(features @ fc1_w + fc1_b)
    gemm_kernel<0, 1><<<dim3(3, 32), blk>>>(features, 768, fc1_w, fc1_b, H, 576,
                                            2048, 192, 768);
    for (int l = 0; l < 2; l++) {
        // giC = Hl @ wih_c^T + bih_c ; ghP = Hl @ whh_p^T + bhh_p
        gemm_kernel<1, 0><<<dim3(9, 32), blk>>>(H + l * 192, 576,
                                                gruc_wih + l * 576 * 192,
                                                gruc_bih + l * 576, GI, 576,
                                                2048, 576, 192);
        gemm_kernel<1, 0><<<dim3(9, 32), blk>>>(H + l * 192, 576,
                                                grup_whh + l * 576 * 192,
                                                grup_bhh + l * 576, GP, 576,
                                                2048, 576, 192);
        ScanArgs SA;
        SA.Hl = H + l * 192;
        SA.adj = adj;
        SA.smask = smask;
        SA.wk = gat_w + l * 384 + 192;
        SA.wr0 = wr0p + l * 192 * 192;
        SA.wr1 = wr1p + l * 192 * 192;
        SA.whhC = gruc_whh + l * 576 * 192;
        SA.wihP = grup_wih + l * 576 * 192;
        SA.bhhC = gruc_bhh + l * 576;
        SA.biP = grup_bih + l * 576;
        SA.giC = GI;
        SA.ghP = GP;
        SA.Hout = H + (l + 1) * 192;
        SA.attnL = attn + l * 65536;
        scan_kernel<<<64, 256, sizeof(SmemScan)>>>(SA);
    }
    // MLP head
    gemm_kernel<0, 1><<<dim3(3, 32), blk>>>(H, 576, mlp_w0, mlp_b0, T0, 192,
                                            2048, 192, 576);
    gemm_kernel<0, 1><<<dim3(3, 32), blk>>>(T0, 192, mlp_w1, mlp_b1, T1, 192,
                                            2048, 192, 192);
    gemm_kernel<0, 0><<<dim3(3, 32), blk>>>(T1, 192, mlp_w2, mlp_b2, logits, 192,
                                            2048, 192, 192);
}